// round 15
// baseline (speedup 1.0000x reference)
#include <cuda_runtime.h>
#include <cuda_bf16.h>
#include <mma.h>
#include <cstdint>

using namespace nvcuda;
using u64 = unsigned long long;
#define FULL_MASK 0xFFFFFFFFu

constexpr int IN_DIM = 256;
constexpr int D = 32;
constexpr float LN_EPS = 1e-5f;

constexpr int TILE_ROWS = 42;          // rows per block tile
constexpr int TILE_RF   = 126;         // 42*3 rf (2 pad rows up to 128)
constexpr int KQ        = 64;          // k-quarter
constexpr int ASTRIDE   = 72;          // bf16 elems per A row (144 B)
constexpr int BSTRIDE   = 260;         // bf16 elems per B row (full K)
constexpr int WSTRIDE   = 36;
constexpr int THREADS   = 256;

// ---- smem layout (bytes) ----
constexpr int OFF_AHI = 0;                                   // 18432
constexpr int OFF_ALO = OFF_AHI + 128 * ASTRIDE * 2;         // 18432
constexpr int OFF_BHI = OFF_ALO + 128 * ASTRIDE * 2;         // 16640
constexpr int OFF_BLO = OFF_BHI + D * BSTRIDE * 2;           // 16640
constexpr int OFF_HB  = OFF_BLO + D * BSTRIDE * 2;           // 16384
constexpr int OFF_W5  = OFF_HB + 128 * D * 4;                // 23040
constexpr int OFF_EPI = OFF_W5 + 5 * D * WSTRIDE * 4;        // 6 slots x 32 f per warp
constexpr int SMEM_SZ = OFF_EPI + 8 * 6 * D * 4;             // 115712 -> 2 blocks/SM

__device__ __forceinline__ void split4(float4 v, uint2& hi, uint2& lo) {
    __nv_bfloat162 h01 = __floats2bfloat162_rn(v.x, v.y);
    __nv_bfloat162 h23 = __floats2bfloat162_rn(v.z, v.w);
    float lx = v.x - __low2float(h01),  ly = v.y - __high2float(h01);
    float lz = v.z - __low2float(h23),  lw = v.w - __high2float(h23);
    __nv_bfloat162 l01 = __floats2bfloat162_rn(lx, ly);
    __nv_bfloat162 l23 = __floats2bfloat162_rn(lz, lw);
    hi.x = *reinterpret_cast<uint32_t*>(&h01);
    hi.y = *reinterpret_cast<uint32_t*>(&h23);
    lo.x = *reinterpret_cast<uint32_t*>(&l01);
    lo.y = *reinterpret_cast<uint32_t*>(&l23);
}
__device__ __forceinline__ void ffma2(u64& d, u64 a, u64 b) {
    asm("fma.rn.f32x2 %0, %1, %2, %0;" : "+l"(d) : "l"(a), "l"(b));
}
__device__ __forceinline__ float hsum2(u64 a, u64 b) {
    return __uint_as_float((unsigned)a) + __uint_as_float((unsigned)(a >> 32))
         + __uint_as_float((unsigned)b) + __uint_as_float((unsigned)(b >> 32));
}
__device__ __forceinline__ float wsum(float v) {
    v += __shfl_xor_sync(FULL_MASK, v, 16);
    v += __shfl_xor_sync(FULL_MASK, v, 8);
    v += __shfl_xor_sync(FULL_MASK, v, 4);
    v += __shfl_xor_sync(FULL_MASK, v, 2);
    v += __shfl_xor_sync(FULL_MASK, v, 1);
    return v;
}

// ================= fused kernel =================
__global__ __launch_bounds__(THREADS, 2)
void fused_kernel(const float* __restrict__ f1, const float* __restrict__ f4,
                  const float* __restrict__ fD,
                  const float* __restrict__ Wp,  const float* __restrict__ bp,
                  const float* __restrict__ ln_g, const float* __restrict__ ln_b,
                  const float* __restrict__ Wq,  const float* __restrict__ bq,
                  const float* __restrict__ Wk,  const float* __restrict__ bk,
                  const float* __restrict__ Wv,  const float* __restrict__ bv,
                  const float* __restrict__ Wo1, const float* __restrict__ bo1,
                  const float* __restrict__ Wo2, const float* __restrict__ bo2,
                  float* __restrict__ out, int B, int ntiles)
{
    extern __shared__ char sm[];
    __nv_bfloat16* Ahi = reinterpret_cast<__nv_bfloat16*>(sm + OFF_AHI);
    __nv_bfloat16* Alo = reinterpret_cast<__nv_bfloat16*>(sm + OFF_ALO);
    __nv_bfloat16* Bhi = reinterpret_cast<__nv_bfloat16*>(sm + OFF_BHI);
    __nv_bfloat16* Blo = reinterpret_cast<__nv_bfloat16*>(sm + OFF_BLO);
    float* hbuf = reinterpret_cast<float*>(sm + OFF_HB);
    float* w5   = reinterpret_cast<float*>(sm + OFF_W5);

    const int tid = threadIdx.x, lane = tid & 31, w = tid >> 5;
    const int nrf = B * 3;
    // per-warp epi scratch: 6 slots of 32 floats
    float* xs = reinterpret_cast<float*>(sm + OFF_EPI) + w * 6 * D;

    // ---- stage Wp hi/lo (full K) + small mats (once) ----
    #pragma unroll
    for (int t = 0; t < 8; t++) {
        int i = tid + t * THREADS;
        int n = i >> 6, c4 = i & 63;
        float4 v = reinterpret_cast<const float4*>(Wp)[i];
        uint2 hi, lo;
        split4(v, hi, lo);
        *reinterpret_cast<uint2*>(&Bhi[n * BSTRIDE + c4 * 4]) = hi;
        *reinterpret_cast<uint2*>(&Blo[n * BSTRIDE + c4 * 4]) = lo;
    }
    for (int i = tid; i < D * D; i += THREADS) {
        int jj = i >> 5, dd = i & 31;
        int o = jj * WSTRIDE + dd;
        w5[0 * D * WSTRIDE + o] = Wq [i];
        w5[1 * D * WSTRIDE + o] = Wk [i];
        w5[2 * D * WSTRIDE + o] = Wv [i];
        w5[3 * D * WSTRIDE + o] = Wo1[i];
        w5[4 * D * WSTRIDE + o] = Wo2[i];
    }
    const float bp_l  = bp [lane];
    const float g_l   = ln_g[lane];
    const float b_l   = ln_b[lane];
    const float bq_l  = bq [lane];
    const float bk_l  = bk [lane];
    const float bv_l  = bv [lane];
    const float bo1_l = bo1[lane];
    const float bo2_l = bo2[lane];

    auto ldg_q = [&](int tile, int q, float4 (&buf)[8]) {
        #pragma unroll
        for (int t = 0; t < 8; t++) {
            int i = tid + t * THREADS;
            int rf_l = i >> 4, c4 = i & 15;
            int rf_g = tile * TILE_RF + rf_l;
            float4 v = make_float4(0.f, 0.f, 0.f, 0.f);
            if (rf_l < TILE_RF && rf_g < nrf) {
                int row = rf_g / 3, ft = rf_g - 3 * row;
                const float* src = (ft == 0) ? f1 : (ft == 1) ? f4 : fD;
                v = reinterpret_cast<const float4*>(src)[row * 64 + q * 16 + c4];
            }
            buf[t] = v;
        }
    };
    auto cvt_q = [&](float4 (&buf)[8]) {
        #pragma unroll
        for (int t = 0; t < 8; t++) {
            int i = tid + t * THREADS;
            int rf_l = i >> 4, c4 = i & 15;
            uint2 hi, lo;
            split4(buf[t], hi, lo);
            *reinterpret_cast<uint2*>(&Ahi[rf_l * ASTRIDE + c4 * 4]) = hi;
            *reinterpret_cast<uint2*>(&Alo[rf_l * ASTRIDE + c4 * 4]) = lo;
        }
    };

    float4 buf[8];
    int tile0 = blockIdx.x;
    if (tile0 < ntiles) ldg_q(tile0, 0, buf);
    __syncthreads();   // B + w5 staged

    for (int tile = tile0; tile < ntiles; tile += gridDim.x) {
        // ============ GEMM phase ============
        wmma::fragment<wmma::accumulator, 16, 16, 16, float> C[2];
        wmma::fill_fragment(C[0], 0.f);
        wmma::fill_fragment(C[1], 0.f);

        #pragma unroll
        for (int q = 0; q < 4; q++) {
            cvt_q(buf);
            if (q < 3) {
                ldg_q(tile, q + 1, buf);
            } else {
                int nt = tile + gridDim.x;
                if (nt < ntiles) ldg_q(nt, 0, buf);
            }
            __syncthreads();   // A quarter ready (also orders prev-tile epi)

            const __nv_bfloat16* Aw_h = Ahi + (w * 16) * ASTRIDE;
            const __nv_bfloat16* Aw_l = Alo + (w * 16) * ASTRIDE;
            const __nv_bfloat16* Bq_h = Bhi + q * KQ;
            const __nv_bfloat16* Bq_l = Blo + q * KQ;
            #pragma unroll
            for (int k = 0; k < KQ / 16; k++) {
                wmma::fragment<wmma::matrix_a, 16, 16, 16, __nv_bfloat16, wmma::row_major> ah, al;
                wmma::load_matrix_sync(ah, Aw_h + k * 16, ASTRIDE);
                wmma::load_matrix_sync(al, Aw_l + k * 16, ASTRIDE);
                #pragma unroll
                for (int n = 0; n < 2; n++) {
                    wmma::fragment<wmma::matrix_b, 16, 16, 16, __nv_bfloat16, wmma::col_major> bh, bl;
                    wmma::load_matrix_sync(bh, Bq_h + n * 16 * BSTRIDE + k * 16, BSTRIDE);
                    wmma::load_matrix_sync(bl, Bq_l + n * 16 * BSTRIDE + k * 16, BSTRIDE);
                    wmma::mma_sync(C[n], ah, bh, C[n]);
                    wmma::mma_sync(C[n], al, bh, C[n]);
                    wmma::mma_sync(C[n], ah, bl, C[n]);
                }
            }
            __syncthreads();   // A consumed
        }

        // C -> hbuf (smem)
        wmma::store_matrix_sync(hbuf + (w * 16) * D,      C[0], D, wmma::mem_row_major);
        wmma::store_matrix_sync(hbuf + (w * 16) * D + 16, C[1], D, wmma::mem_row_major);
        __syncthreads();   // hbuf ready

        // ============ epilogue: 2 rows per warp per pass ============
        const int row0 = tile * TILE_ROWS;
        const int rows_here = (B - row0 < TILE_ROWS) ? (B - row0) : TILE_ROWS;

        for (int rp = w * 2; rp < rows_here; rp += 16) {
            const int nr = (rows_here - rp >= 2) ? 2 : 1;
            const int nu = nr * 3;

            // ---- bias + relu + LN for up to 6 vectors (pipelined chains) ----
            #pragma unroll
            for (int u = 0; u < 6; u++) {
                if (u >= nu) break;
                float h = hbuf[((rp + (u >= 3)) * 3 + (u % 3)) * D + lane] + bp_l;
                h = fmaxf(h, 0.f);
                float s1 = wsum(h);
                float s2 = wsum(h * h);
                float mu  = s1 * (1.f / 32.f);
                float var = fmaxf(s2 * (1.f / 32.f) - mu * mu, 0.f);
                xs[u * D + lane] = g_l * (h - mu) * rsqrtf(var + LN_EPS) + b_l;
            }
            __syncwarp();

            // ---- QKV: weight loads amortized over 6 x-vectors ----
            float qkvr[3][6];
            float bias3[3] = { bq_l, bk_l, bv_l };
            #pragma unroll
            for (int mat = 0; mat < 3; mat++) {
                const ulonglong2* wrow = reinterpret_cast<const ulonglong2*>(
                    w5 + mat * D * WSTRIDE + lane * WSTRIDE);
                u64 a0[6] = {0,0,0,0,0,0}, a1[6] = {0,0,0,0,0,0};
                #pragma unroll
                for (int c = 0; c < 8; c++) {
                    ulonglong2 wv = wrow[c];
                    #pragma unroll
                    for (int u = 0; u < 6; u++) {
                        ulonglong2 xv = reinterpret_cast<const ulonglong2*>(xs + u * D)[c];
                        ffma2(a0[u], wv.x, xv.x);
                        ffma2(a1[u], wv.y, xv.y);
                    }
                }
                #pragma unroll
                for (int u = 0; u < 6; u++)
                    qkvr[mat][u] = hsum2(a0[u], a1[u]) + bias3[mat];
            }
            __syncwarp();     // xs consumed; slots reusable for pp/o1

            // ---- attention + softmax + pool (both rows; wsums pipeline) ----
            const float scale = 0.17677669529663687f;   // 1/sqrt(32)
            float att[2][3][3];
            #pragma unroll
            for (int r = 0; r < 2; r++)
                #pragma unroll
                for (int ss = 0; ss < 3; ss++)
                    #pragma unroll
                    for (int tt = 0; tt < 3; tt++)
                        att[r][ss][tt] = wsum(qkvr[0][r * 3 + ss] * qkvr[1][r * 3 + tt]) * scale;

            float poolr[2];
            #pragma unroll
            for (int r = 0; r < 2; r++) {
                float pool = 0.f;
                #pragma unroll
                for (int ss = 0; ss < 3; ss++) {
                    float m  = fmaxf(att[r][ss][0], fmaxf(att[r][ss][1], att[r][ss][2]));
                    float e0 = __expf(att[r][ss][0] - m);
                    float e1 = __expf(att[r][ss][1] - m);
                    float e2 = __expf(att[r][ss][2] - m);
                    float ri = 1.f / (e0 + e1 + e2);
                    pool += (e0 * qkvr[2][r * 3 + 0] + e1 * qkvr[2][r * 3 + 1]
                           + e2 * qkvr[2][r * 3 + 2]) * ri;
                }
                poolr[r] = pool * (1.f / 3.f);
                xs[r * D + lane] = poolr[r];      // pp -> slots 0,1
            }
            __syncwarp();

            // ---- O1 (amortized over 2 rows) ----
            {
                const ulonglong2* w1 = reinterpret_cast<const ulonglong2*>(
                    w5 + 3 * D * WSTRIDE + lane * WSTRIDE);
                u64 a0[2] = {0, 0}, a1[2] = {0, 0};
                #pragma unroll
                for (int c = 0; c < 8; c++) {
                    ulonglong2 wv = w1[c];
                    #pragma unroll
                    for (int r = 0; r < 2; r++) {
                        ulonglong2 xv = reinterpret_cast<const ulonglong2*>(xs + r * D)[c];
                        ffma2(a0[r], wv.x, xv.x);
                        ffma2(a1[r], wv.y, xv.y);
                    }
                }
                #pragma unroll
                for (int r = 0; r < 2; r++)
                    xs[(2 + r) * D + lane] =                 // o1 -> slots 2,3
                        fmaxf(hsum2(a0[r], a1[r]) + bo1_l, 0.f);
            }
            __syncwarp();

            // ---- O2 + residual + store ----
            {
                const ulonglong2* w2 = reinterpret_cast<const ulonglong2*>(
                    w5 + 4 * D * WSTRIDE + lane * WSTRIDE);
                u64 a0[2] = {0, 0}, a1[2] = {0, 0};
                #pragma unroll
                for (int c = 0; c < 8; c++) {
                    ulonglong2 wv = w2[c];
                    #pragma unroll
                    for (int r = 0; r < 2; r++) {
                        ulonglong2 xv = reinterpret_cast<const ulonglong2*>(xs + (2 + r) * D)[c];
                        ffma2(a0[r], wv.x, xv.x);
                        ffma2(a1[r], wv.y, xv.y);
                    }
                }
                #pragma unroll
                for (int r = 0; r < 2; r++)
                    if (r < nr)
                        out[(size_t)(row0 + rp + r) * D + lane] =
                            hsum2(a0[r], a1[r]) + bo2_l + poolr[r];
            }
            __syncwarp();
        }
        // no end-of-tile barrier: epi scratch dedicated; next tile's GEMM
        // barriers provide ordering.
    }
}

// ================= launch =================
extern "C" void kernel_launch(void* const* d_in, const int* in_sizes, int n_in,
                              void* d_out, int out_size)
{
    const float* f1   = (const float*)d_in[0];
    const float* f4   = (const float*)d_in[1];
    const float* fD   = (const float*)d_in[2];
    const float* Wp   = (const float*)d_in[3];
    const float* bp   = (const float*)d_in[4];
    const float* ln_g = (const float*)d_in[5];
    const float* ln_b = (const float*)d_in[6];
    const float* Wq   = (const float*)d_in[7];
    const float* bq   = (const float*)d_in[8];
    const float* Wk   = (const float*)d_in[9];
    const float* bk   = (const float*)d_in[10];
    const float* Wv   = (const float*)d_in[11];
    const float* bv   = (const float*)d_in[12];
    const float* Wo1  = (const float*)d_in[13];
    const float* bo1  = (const float*)d_in[14];
    const float* Wo2  = (const float*)d_in[15];
    const float* bo2  = (const float*)d_in[16];

    const int B = in_sizes[0] / IN_DIM;
    const int ntiles = (B + TILE_ROWS - 1) / TILE_ROWS;

    cudaFuncSetAttribute(fused_kernel, cudaFuncAttributeMaxDynamicSharedMemorySize, SMEM_SZ);

    int grid = ntiles < 304 ? ntiles : 304;   // 2 blocks x 152 SMs
    fused_kernel<<<grid, THREADS, SMEM_SZ>>>(
        f1, f4, fD, Wp, bp, ln_g, ln_b, Wq, bq, Wk, bk, Wv, bv,
        Wo1, bo1, Wo2, bo2, (float*)d_out, B, ntiles);
}

// round 16
// speedup vs baseline: 1.9943x; 1.9943x over previous
#include <cuda_runtime.h>
#include <cuda_bf16.h>
#include <mma.h>
#include <cstdint>

using namespace nvcuda;
using u64 = unsigned long long;
#define FULL_MASK 0xFFFFFFFFu

constexpr int IN_DIM = 256;
constexpr int D = 32;
constexpr float LN_EPS = 1e-5f;

constexpr int TILE_ROWS = 36;          // rows per block tile (1821 tiles ~ 304*5.99)
constexpr int TILE_RF   = 108;         // 36*3 rf (padded to 128 in A/C)
constexpr int KQ        = 64;          // k-quarter
constexpr int ASTRIDE   = 72;          // bf16 elems per A row (144 B)
constexpr int BSTRIDE   = 260;         // bf16 elems per B row (full K)
constexpr int WSTRIDE   = 36;
constexpr int THREADS   = 256;

// ---- smem layout (bytes) ----
constexpr int OFF_AHI = 0;                                   // 18432
constexpr int OFF_ALO = OFF_AHI + 128 * ASTRIDE * 2;         // 18432
constexpr int OFF_BHI = OFF_ALO + 128 * ASTRIDE * 2;         // 16640
constexpr int OFF_BLO = OFF_BHI + D * BSTRIDE * 2;           // 16640
constexpr int OFF_HB  = OFF_BLO + D * BSTRIDE * 2;           // 16384
constexpr int OFF_W5  = OFF_HB + 128 * D * 4;                // 23040
constexpr int OFF_EPI = OFF_W5 + 5 * D * WSTRIDE * 4;        // epi scratch
constexpr int OFF_XB  = OFF_EPI;                             // 8*3*32*4 = 3072
constexpr int OFF_PP  = OFF_EPI + 3072;                      // 1024
constexpr int OFF_O1  = OFF_EPI + 4096;                      // 1024
constexpr int SMEM_SZ = OFF_EPI + 5120;                      // 114688 -> 2 blocks/SM

__device__ __forceinline__ void split4(float4 v, uint2& hi, uint2& lo) {
    __nv_bfloat162 h01 = __floats2bfloat162_rn(v.x, v.y);
    __nv_bfloat162 h23 = __floats2bfloat162_rn(v.z, v.w);
    float lx = v.x - __low2float(h01),  ly = v.y - __high2float(h01);
    float lz = v.z - __low2float(h23),  lw = v.w - __high2float(h23);
    __nv_bfloat162 l01 = __floats2bfloat162_rn(lx, ly);
    __nv_bfloat162 l23 = __floats2bfloat162_rn(lz, lw);
    hi.x = *reinterpret_cast<uint32_t*>(&h01);
    hi.y = *reinterpret_cast<uint32_t*>(&h23);
    lo.x = *reinterpret_cast<uint32_t*>(&l01);
    lo.y = *reinterpret_cast<uint32_t*>(&l23);
}
__device__ __forceinline__ void ffma2(u64& d, u64 a, u64 b) {
    asm("fma.rn.f32x2 %0, %1, %2, %0;" : "+l"(d) : "l"(a), "l"(b));
}
__device__ __forceinline__ float hsum2(u64 a, u64 b) {
    return __uint_as_float((unsigned)a) + __uint_as_float((unsigned)(a >> 32))
         + __uint_as_float((unsigned)b) + __uint_as_float((unsigned)(b >> 32));
}
__device__ __forceinline__ float wsum(float v) {
    v += __shfl_xor_sync(FULL_MASK, v, 16);
    v += __shfl_xor_sync(FULL_MASK, v, 8);
    v += __shfl_xor_sync(FULL_MASK, v, 4);
    v += __shfl_xor_sync(FULL_MASK, v, 2);
    v += __shfl_xor_sync(FULL_MASK, v, 1);
    return v;
}

// ================= fused kernel =================
__global__ __launch_bounds__(THREADS, 2)
void fused_kernel(const float* __restrict__ f1, const float* __restrict__ f4,
                  const float* __restrict__ fD,
                  const float* __restrict__ Wp,  const float* __restrict__ bp,
                  const float* __restrict__ ln_g, const float* __restrict__ ln_b,
                  const float* __restrict__ Wq,  const float* __restrict__ bq,
                  const float* __restrict__ Wk,  const float* __restrict__ bk,
                  const float* __restrict__ Wv,  const float* __restrict__ bv,
                  const float* __restrict__ Wo1, const float* __restrict__ bo1,
                  const float* __restrict__ Wo2, const float* __restrict__ bo2,
                  float* __restrict__ out, int B, int ntiles)
{
    extern __shared__ char sm[];
    __nv_bfloat16* Ahi = reinterpret_cast<__nv_bfloat16*>(sm + OFF_AHI);
    __nv_bfloat16* Alo = reinterpret_cast<__nv_bfloat16*>(sm + OFF_ALO);
    __nv_bfloat16* Bhi = reinterpret_cast<__nv_bfloat16*>(sm + OFF_BHI);
    __nv_bfloat16* Blo = reinterpret_cast<__nv_bfloat16*>(sm + OFF_BLO);
    float* hbuf = reinterpret_cast<float*>(sm + OFF_HB);
    float* w5   = reinterpret_cast<float*>(sm + OFF_W5);
    float* xbuf = reinterpret_cast<float*>(sm + OFF_XB);
    float* pp   = reinterpret_cast<float*>(sm + OFF_PP);
    float* o1s  = reinterpret_cast<float*>(sm + OFF_O1);

    const int tid = threadIdx.x, lane = tid & 31, w = tid >> 5;
    const int nrf = B * 3;
    const int c4t = tid & 15;          // column float4-slot within quarter

    // ---- stage Wp hi/lo (full K) + small mats (once) ----
    #pragma unroll
    for (int t = 0; t < 8; t++) {
        int i = tid + t * THREADS;
        int n = i >> 6, c4 = i & 63;
        float4 v = reinterpret_cast<const float4*>(Wp)[i];
        uint2 hi, lo;
        split4(v, hi, lo);
        *reinterpret_cast<uint2*>(&Bhi[n * BSTRIDE + c4 * 4]) = hi;
        *reinterpret_cast<uint2*>(&Blo[n * BSTRIDE + c4 * 4]) = lo;
    }
    for (int i = tid; i < D * D; i += THREADS) {
        int jj = i >> 5, dd = i & 31;
        int o = jj * WSTRIDE + dd;
        w5[0 * D * WSTRIDE + o] = Wq [i];
        w5[1 * D * WSTRIDE + o] = Wk [i];
        w5[2 * D * WSTRIDE + o] = Wv [i];
        w5[3 * D * WSTRIDE + o] = Wo1[i];
        w5[4 * D * WSTRIDE + o] = Wo2[i];
    }
    const float bp_l  = bp [lane];
    const float g_l   = ln_g[lane];
    const float b_l   = ln_b[lane];
    const float bq_l  = bq [lane];
    const float bk_l  = bk [lane];
    const float bv_l  = bv [lane];
    const float bo1_l = bo1[lane];
    const float bo2_l = bo2[lane];

    // ---- per-tile slot precompute: byte offsets + packed feat selector ----
    // slot t: rf_l = (tid>>4) + t*16, c4 = tid&15 (t-invariant), rf padded rows clamped
    int off32[8];
    unsigned ftpack = 0;
    auto precompute = [&](int tile) {
        ftpack = 0;
        #pragma unroll
        for (int t = 0; t < 8; t++) {
            int rf_l = (tid >> 4) + t * 16;
            int rf_g = tile * TILE_RF + rf_l;
            rf_g = (rf_g < nrf - 1) ? rf_g : (nrf - 1);   // clamp (garbage rows unread)
            int row = rf_g / 3;
            int ft  = rf_g - 3 * row;
            off32[t] = (row * 64 + c4t) * 16;             // byte offset of float4
            ftpack |= (unsigned)ft << (t * 4);
        }
    };
    auto ldg_q = [&](int q, float4 (&buf)[8]) {
        #pragma unroll
        for (int t = 0; t < 8; t++) {
            unsigned ft = (ftpack >> (t * 4)) & 3u;
            const float* src = (ft == 0) ? f1 : (ft == 1) ? f4 : fD;
            buf[t] = *reinterpret_cast<const float4*>(
                reinterpret_cast<const char*>(src) + off32[t] + q * 256);
        }
    };
    auto cvt_q = [&](float4 (&buf)[8]) {
        #pragma unroll
        for (int t = 0; t < 8; t++) {
            int rf_l = (tid >> 4) + t * 16;
            uint2 hi, lo;
            split4(buf[t], hi, lo);
            *reinterpret_cast<uint2*>(&Ahi[rf_l * ASTRIDE + c4t * 4]) = hi;
            *reinterpret_cast<uint2*>(&Alo[rf_l * ASTRIDE + c4t * 4]) = lo;
        }
    };

    float4 buf[8];
    int tile0 = blockIdx.x;
    if (tile0 < ntiles) { precompute(tile0); ldg_q(0, buf); }
    __syncthreads();   // B + w5 staged

    for (int tile = tile0; tile < ntiles; tile += gridDim.x) {
        // ============ GEMM phase ============
        wmma::fragment<wmma::accumulator, 16, 16, 16, float> C[2];
        wmma::fill_fragment(C[0], 0.f);
        wmma::fill_fragment(C[1], 0.f);

        #pragma unroll
        for (int q = 0; q < 4; q++) {
            cvt_q(buf);
            if (q < 3) {
                ldg_q(q + 1, buf);
            } else {
                int nt = tile + gridDim.x;
                if (nt < ntiles) { precompute(nt); ldg_q(0, buf); }
            }
            __syncthreads();   // A quarter ready (also orders prev-tile epi)

            const __nv_bfloat16* Aw_h = Ahi + (w * 16) * ASTRIDE;
            const __nv_bfloat16* Aw_l = Alo + (w * 16) * ASTRIDE;
            const __nv_bfloat16* Bq_h = Bhi + q * KQ;
            const __nv_bfloat16* Bq_l = Blo + q * KQ;
            #pragma unroll
            for (int k = 0; k < KQ / 16; k++) {
                wmma::fragment<wmma::matrix_a, 16, 16, 16, __nv_bfloat16, wmma::row_major> ah, al;
                wmma::load_matrix_sync(ah, Aw_h + k * 16, ASTRIDE);
                wmma::load_matrix_sync(al, Aw_l + k * 16, ASTRIDE);
                #pragma unroll
                for (int n = 0; n < 2; n++) {
                    wmma::fragment<wmma::matrix_b, 16, 16, 16, __nv_bfloat16, wmma::col_major> bh, bl;
                    wmma::load_matrix_sync(bh, Bq_h + n * 16 * BSTRIDE + k * 16, BSTRIDE);
                    wmma::load_matrix_sync(bl, Bq_l + n * 16 * BSTRIDE + k * 16, BSTRIDE);
                    wmma::mma_sync(C[n], ah, bh, C[n]);
                    wmma::mma_sync(C[n], al, bh, C[n]);
                    wmma::mma_sync(C[n], ah, bl, C[n]);
                }
            }
            __syncthreads();   // A consumed
        }

        // C -> hbuf (smem)
        wmma::store_matrix_sync(hbuf + (w * 16) * D,      C[0], D, wmma::mem_row_major);
        wmma::store_matrix_sync(hbuf + (w * 16) * D + 16, C[1], D, wmma::mem_row_major);
        __syncthreads();   // hbuf ready

        // ============ epilogue phase (warp-autonomous; no end barrier) ============
        const int row0 = tile * TILE_ROWS;
        const int rows_here = (B - row0 < TILE_ROWS) ? (B - row0) : TILE_ROWS;

        for (int r = w; r < rows_here; r += 8) {
            // ---- bias + relu + LN (parallel sum / sumsq) ----
            #pragma unroll
            for (int s = 0; s < 3; s++) {
                float h = hbuf[(r * 3 + s) * D + lane] + bp_l;
                h = fmaxf(h, 0.f);
                float s1 = wsum(h);
                float s2 = wsum(h * h);
                float mu  = s1 * (1.f / 32.f);
                float var = fmaxf(s2 * (1.f / 32.f) - mu * mu, 0.f);
                xbuf[(w * 3 + s) * D + lane] =
                    g_l * (h - mu) * rsqrtf(var + LN_EPS) + b_l;
            }
            __syncwarp();

            // ---- QKV ----
            float qkvr[3][3];
            float bias3[3] = { bq_l, bk_l, bv_l };
            #pragma unroll
            for (int mat = 0; mat < 3; mat++) {
                const ulonglong2* wrow = reinterpret_cast<const ulonglong2*>(
                    w5 + mat * D * WSTRIDE + lane * WSTRIDE);
                u64 a0[3] = {0ull,0ull,0ull}, a1[3] = {0ull,0ull,0ull};
                #pragma unroll
                for (int c = 0; c < 8; c++) {
                    ulonglong2 wv = wrow[c];
                    #pragma unroll
                    for (int ss = 0; ss < 3; ss++) {
                        ulonglong2 xv = reinterpret_cast<const ulonglong2*>(
                            xbuf + (w * 3 + ss) * D)[c];
                        ffma2(a0[ss], wv.x, xv.x);
                        ffma2(a1[ss], wv.y, xv.y);
                    }
                }
                #pragma unroll
                for (int ss = 0; ss < 3; ss++)
                    qkvr[mat][ss] = hsum2(a0[ss], a1[ss]) + bias3[mat];
            }

            // ---- attention + softmax + pool ----
            const float scale = 0.17677669529663687f;   // 1/sqrt(32)
            float att[3][3];
            #pragma unroll
            for (int ss = 0; ss < 3; ss++)
                #pragma unroll
                for (int tt = 0; tt < 3; tt++)
                    att[ss][tt] = wsum(qkvr[0][ss] * qkvr[1][tt]) * scale;

            float pool = 0.f;
            #pragma unroll
            for (int ss = 0; ss < 3; ss++) {
                float m  = fmaxf(att[ss][0], fmaxf(att[ss][1], att[ss][2]));
                float e0 = __expf(att[ss][0] - m);
                float e1 = __expf(att[ss][1] - m);
                float e2 = __expf(att[ss][2] - m);
                float ri = 1.f / (e0 + e1 + e2);
                pool += (e0 * qkvr[2][0] + e1 * qkvr[2][1] + e2 * qkvr[2][2]) * ri;
            }
            pool *= (1.f / 3.f);
            pp[w * D + lane] = pool;
            __syncwarp();

            // ---- O1 ----
            {
                const ulonglong2* pv = reinterpret_cast<const ulonglong2*>(pp + w * D);
                const ulonglong2* w1 = reinterpret_cast<const ulonglong2*>(
                    w5 + 3 * D * WSTRIDE + lane * WSTRIDE);
                u64 a0 = 0ull, a1 = 0ull;
                #pragma unroll
                for (int c = 0; c < 8; c++) {
                    ulonglong2 pvv = pv[c], wv = w1[c];
                    ffma2(a0, wv.x, pvv.x);
                    ffma2(a1, wv.y, pvv.y);
                }
                o1s[w * D + lane] = fmaxf(hsum2(a0, a1) + bo1_l, 0.f);
            }
            __syncwarp();

            // ---- O2 + residual + store ----
            {
                const ulonglong2* ov = reinterpret_cast<const ulonglong2*>(o1s + w * D);
                const ulonglong2* w2 = reinterpret_cast<const ulonglong2*>(
                    w5 + 4 * D * WSTRIDE + lane * WSTRIDE);
                u64 a0 = 0ull, a1 = 0ull;
                #pragma unroll
                for (int c = 0; c < 8; c++) {
                    ulonglong2 ovv = ov[c], wv = w2[c];
                    ffma2(a0, wv.x, ovv.x);
                    ffma2(a1, wv.y, ovv.y);
                }
                out[(size_t)(row0 + r) * D + lane] = hsum2(a0, a1) + bo2_l + pool;
            }
            __syncwarp();
        }
        // no end-of-tile barrier: epi scratch dedicated; next tile's GEMM
        // barriers provide ordering.
    }
}

// ================= launch =================
extern "C" void kernel_launch(void* const* d_in, const int* in_sizes, int n_in,
                              void* d_out, int out_size)
{
    const float* f1   = (const float*)d_in[0];
    const float* f4   = (const float*)d_in[1];
    const float* fD   = (const float*)d_in[2];
    const float* Wp   = (const float*)d_in[3];
    const float* bp   = (const float*)d_in[4];
    const float* ln_g = (const float*)d_in[5];
    const float* ln_b = (const float*)d_in[6];
    const float* Wq   = (const float*)d_in[7];
    const float* bq   = (const float*)d_in[8];
    const float* Wk   = (const float*)d_in[9];
    const float* bk   = (const float*)d_in[10];
    const float* Wv   = (const float*)d_in[11];
    const float* bv   = (const float*)d_in[12];
    const float* Wo1  = (const float*)d_in[13];
    const float* bo1  = (const float*)d_in[14];
    const float* Wo2  = (const float*)d_in[15];
    const float* bo2  = (const float*)d_in[16];

    const int B = in_sizes[0] / IN_DIM;
    const int ntiles = (B + TILE_ROWS - 1) / TILE_ROWS;

    cudaFuncSetAttribute(fused_kernel, cudaFuncAttributeMaxDynamicSharedMemorySize, SMEM_SZ);

    int grid = ntiles < 304 ? ntiles : 304;   // 2 blocks x 152 SMs
    fused_kernel<<<grid, THREADS, SMEM_SZ>>>(
        f1, f4, fD, Wp, bp, ln_g, ln_b, Wq, bq, Wk, bk, Wv, bv,
        Wo1, bo1, Wo2, bo2, (float*)d_out, B, ntiles);
}

// round 17
// speedup vs baseline: 2.0427x; 1.0243x over previous
#include <cuda_runtime.h>
#include <cuda_bf16.h>
#include <mma.h>
#include <cstdint>

using namespace nvcuda;
using u64 = unsigned long long;
#define FULL_MASK 0xFFFFFFFFu

constexpr int IN_DIM = 256;
constexpr int D = 32;
constexpr float LN_EPS = 1e-5f;

constexpr int TILE_ROWS = 42;          // rows per block tile
constexpr int TILE_RF   = 126;         // 42*3 rf (padded to 128)
constexpr int KQ        = 64;          // k-quarter
constexpr int ASTRIDE   = 72;          // bf16 elems per A row (144 B)
constexpr int BSTRIDE   = 260;         // bf16 elems per B row (full K)
constexpr int WSTRIDE   = 36;
constexpr int THREADS   = 256;

// ---- smem layout (bytes) ----
constexpr int OFF_AHI = 0;                                   // 18432
constexpr int OFF_ALO = OFF_AHI + 128 * ASTRIDE * 2;         // 18432
constexpr int OFF_BHI = OFF_ALO + 128 * ASTRIDE * 2;         // 16640
constexpr int OFF_BLO = OFF_BHI + D * BSTRIDE * 2;           // 16640
constexpr int OFF_HB  = OFF_BLO + D * BSTRIDE * 2;           // 16384
constexpr int OFF_W5  = OFF_HB + 128 * D * 4;                // 23040
constexpr int OFF_EPI = OFF_W5 + 5 * D * WSTRIDE * 4;        // 3 slots x 32 f per warp
constexpr int SMEM_SZ = OFF_EPI + 8 * 3 * D * 4;             // 112640 -> 2 blocks/SM

__device__ __forceinline__ void split4(float4 v, uint2& hi, uint2& lo) {
    __nv_bfloat162 h01 = __floats2bfloat162_rn(v.x, v.y);
    __nv_bfloat162 h23 = __floats2bfloat162_rn(v.z, v.w);
    float lx = v.x - __low2float(h01),  ly = v.y - __high2float(h01);
    float lz = v.z - __low2float(h23),  lw = v.w - __high2float(h23);
    __nv_bfloat162 l01 = __floats2bfloat162_rn(lx, ly);
    __nv_bfloat162 l23 = __floats2bfloat162_rn(lz, lw);
    hi.x = *reinterpret_cast<uint32_t*>(&h01);
    hi.y = *reinterpret_cast<uint32_t*>(&h23);
    lo.x = *reinterpret_cast<uint32_t*>(&l01);
    lo.y = *reinterpret_cast<uint32_t*>(&l23);
}
__device__ __forceinline__ void ffma2(u64& d, u64 a, u64 b) {
    asm("fma.rn.f32x2 %0, %1, %2, %0;" : "+l"(d) : "l"(a), "l"(b));
}
__device__ __forceinline__ float hsum2(u64 a, u64 b) {
    return __uint_as_float((unsigned)a) + __uint_as_float((unsigned)(a >> 32))
         + __uint_as_float((unsigned)b) + __uint_as_float((unsigned)(b >> 32));
}
__device__ __forceinline__ float wsum(float v) {
    v += __shfl_xor_sync(FULL_MASK, v, 16);
    v += __shfl_xor_sync(FULL_MASK, v, 8);
    v += __shfl_xor_sync(FULL_MASK, v, 4);
    v += __shfl_xor_sync(FULL_MASK, v, 2);
    v += __shfl_xor_sync(FULL_MASK, v, 1);
    return v;
}

// ================= fused kernel =================
__global__ __launch_bounds__(THREADS, 2)
void fused_kernel(const float* __restrict__ f1, const float* __restrict__ f4,
                  const float* __restrict__ fD,
                  const float* __restrict__ Wp,  const float* __restrict__ bp,
                  const float* __restrict__ ln_g, const float* __restrict__ ln_b,
                  const float* __restrict__ Wq,  const float* __restrict__ bq,
                  const float* __restrict__ Wk,  const float* __restrict__ bk,
                  const float* __restrict__ Wv,  const float* __restrict__ bv,
                  const float* __restrict__ Wo1, const float* __restrict__ bo1,
                  const float* __restrict__ Wo2, const float* __restrict__ bo2,
                  float* __restrict__ out, int B, int ntiles)
{
    extern __shared__ char sm[];
    __nv_bfloat16* Ahi = reinterpret_cast<__nv_bfloat16*>(sm + OFF_AHI);
    __nv_bfloat16* Alo = reinterpret_cast<__nv_bfloat16*>(sm + OFF_ALO);
    __nv_bfloat16* Bhi = reinterpret_cast<__nv_bfloat16*>(sm + OFF_BHI);
    __nv_bfloat16* Blo = reinterpret_cast<__nv_bfloat16*>(sm + OFF_BLO);
    float* hbuf = reinterpret_cast<float*>(sm + OFF_HB);
    float* w5   = reinterpret_cast<float*>(sm + OFF_W5);

    const int tid = threadIdx.x, lane = tid & 31, w = tid >> 5;
    const int nrf = B * 3;
    const int c4t = tid & 15;
    float* xs = reinterpret_cast<float*>(sm + OFF_EPI) + w * 3 * D;   // 3 slots/warp

    // ---- stage Wp hi/lo (full K) + small mats (once) ----
    #pragma unroll
    for (int t = 0; t < 8; t++) {
        int i = tid + t * THREADS;
        int n = i >> 6, c4 = i & 63;
        float4 v = reinterpret_cast<const float4*>(Wp)[i];
        uint2 hi, lo;
        split4(v, hi, lo);
        *reinterpret_cast<uint2*>(&Bhi[n * BSTRIDE + c4 * 4]) = hi;
        *reinterpret_cast<uint2*>(&Blo[n * BSTRIDE + c4 * 4]) = lo;
    }
    for (int i = tid; i < D * D; i += THREADS) {
        int jj = i >> 5, dd = i & 31;
        int o = jj * WSTRIDE + dd;
        w5[0 * D * WSTRIDE + o] = Wq [i];
        w5[1 * D * WSTRIDE + o] = Wk [i];
        w5[2 * D * WSTRIDE + o] = Wv [i];
        w5[3 * D * WSTRIDE + o] = Wo1[i];
        w5[4 * D * WSTRIDE + o] = Wo2[i];
    }
    const float bp_l  = bp [lane];
    const float g_l   = ln_g[lane];
    const float b_l   = ln_b[lane];
    const float bq_l  = bq [lane];
    const float bk_l  = bk [lane];
    const float bv_l  = bv [lane];
    const float bo1_l = bo1[lane];
    const float bo2_l = bo2[lane];

    // ---- per-tile slot precompute (R16): byte offsets + packed feat selector ----
    int off32[8];
    unsigned ftpack = 0;
    auto precompute = [&](int tile) {
        ftpack = 0;
        #pragma unroll
        for (int t = 0; t < 8; t++) {
            int rf_l = (tid >> 4) + t * 16;
            int rf_g = tile * TILE_RF + rf_l;
            rf_g = (rf_g < nrf - 1) ? rf_g : (nrf - 1);   // clamp (garbage rows unread)
            int row = rf_g / 3;
            int ft  = rf_g - 3 * row;
            off32[t] = (row * 64 + c4t) * 16;
            ftpack |= (unsigned)ft << (t * 4);
        }
    };
    auto ldg_q = [&](int q, float4 (&buf)[8]) {
        #pragma unroll
        for (int t = 0; t < 8; t++) {
            unsigned ft = (ftpack >> (t * 4)) & 3u;
            const float* src = (ft == 0) ? f1 : (ft == 1) ? f4 : fD;
            buf[t] = *reinterpret_cast<const float4*>(
                reinterpret_cast<const char*>(src) + off32[t] + q * 256);
        }
    };
    auto cvt_q = [&](float4 (&buf)[8]) {
        #pragma unroll
        for (int t = 0; t < 8; t++) {
            int rf_l = (tid >> 4) + t * 16;
            uint2 hi, lo;
            split4(buf[t], hi, lo);
            *reinterpret_cast<uint2*>(&Ahi[rf_l * ASTRIDE + c4t * 4]) = hi;
            *reinterpret_cast<uint2*>(&Alo[rf_l * ASTRIDE + c4t * 4]) = lo;
        }
    };

    float4 buf[8];
    int tile0 = blockIdx.x;
    if (tile0 < ntiles) { precompute(tile0); ldg_q(0, buf); }
    __syncthreads();   // B + w5 staged

    for (int tile = tile0; tile < ntiles; tile += gridDim.x) {
        // ============ GEMM phase ============
        wmma::fragment<wmma::accumulator, 16, 16, 16, float> C[2];
        wmma::fill_fragment(C[0], 0.f);
        wmma::fill_fragment(C[1], 0.f);

        #pragma unroll
        for (int q = 0; q < 4; q++) {
            cvt_q(buf);
            if (q < 3) {
                ldg_q(q + 1, buf);
            } else {
                int nt = tile + gridDim.x;
                if (nt < ntiles) { precompute(nt); ldg_q(0, buf); }
            }
            __syncthreads();   // A quarter ready (also orders prev-tile epi)

            const __nv_bfloat16* Aw_h = Ahi + (w * 16) * ASTRIDE;
            const __nv_bfloat16* Aw_l = Alo + (w * 16) * ASTRIDE;
            const __nv_bfloat16* Bq_h = Bhi + q * KQ;
            const __nv_bfloat16* Bq_l = Blo + q * KQ;
            #pragma unroll
            for (int k = 0; k < KQ / 16; k++) {
                wmma::fragment<wmma::matrix_a, 16, 16, 16, __nv_bfloat16, wmma::row_major> ah, al;
                wmma::load_matrix_sync(ah, Aw_h + k * 16, ASTRIDE);
                wmma::load_matrix_sync(al, Aw_l + k * 16, ASTRIDE);
                #pragma unroll
                for (int n = 0; n < 2; n++) {
                    wmma::fragment<wmma::matrix_b, 16, 16, 16, __nv_bfloat16, wmma::col_major> bh, bl;
                    wmma::load_matrix_sync(bh, Bq_h + n * 16 * BSTRIDE + k * 16, BSTRIDE);
                    wmma::load_matrix_sync(bl, Bq_l + n * 16 * BSTRIDE + k * 16, BSTRIDE);
                    wmma::mma_sync(C[n], ah, bh, C[n]);
                    wmma::mma_sync(C[n], al, bh, C[n]);
                    wmma::mma_sync(C[n], ah, bl, C[n]);
                }
            }
            __syncthreads();   // A consumed
        }

        // C -> hbuf (smem)
        wmma::store_matrix_sync(hbuf + (w * 16) * D,      C[0], D, wmma::mem_row_major);
        wmma::store_matrix_sync(hbuf + (w * 16) * D + 16, C[1], D, wmma::mem_row_major);
        __syncthreads();   // hbuf ready

        // ============ epilogue: row pairs (r, r+8) per warp ============
        const int row0 = tile * TILE_ROWS;
        const int rows_here = (B - row0 < TILE_ROWS) ? (B - row0) : TILE_ROWS;

        for (int r = w; r < rows_here; r += 16) {
            const int nr = (r + 8 < rows_here) ? 2 : 1;
            float poolr[2];

            // ---- per-row LN + QKV + attention (sequential; regs stay small) ----
            #pragma unroll
            for (int rr = 0; rr < 2; rr++) {
                if (rr >= nr) { poolr[rr] = 0.f; break; }
                const int rrow = r + rr * 8;

                #pragma unroll
                for (int s = 0; s < 3; s++) {
                    float h = hbuf[(rrow * 3 + s) * D + lane] + bp_l;
                    h = fmaxf(h, 0.f);
                    float s1 = wsum(h);
                    float s2 = wsum(h * h);
                    float mu  = s1 * (1.f / 32.f);
                    float var = fmaxf(s2 * (1.f / 32.f) - mu * mu, 0.f);
                    xs[s * D + lane] = g_l * (h - mu) * rsqrtf(var + LN_EPS) + b_l;
                }
                __syncwarp();

                float qkvr[3][3];
                float bias3[3] = { bq_l, bk_l, bv_l };
                #pragma unroll
                for (int mat = 0; mat < 3; mat++) {
                    const ulonglong2* wrow = reinterpret_cast<const ulonglong2*>(
                        w5 + mat * D * WSTRIDE + lane * WSTRIDE);
                    u64 a0[3] = {0ull,0ull,0ull}, a1[3] = {0ull,0ull,0ull};
                    #pragma unroll
                    for (int c = 0; c < 8; c++) {
                        ulonglong2 wv = wrow[c];
                        #pragma unroll
                        for (int ss = 0; ss < 3; ss++) {
                            ulonglong2 xv = reinterpret_cast<const ulonglong2*>(
                                xs + ss * D)[c];
                            ffma2(a0[ss], wv.x, xv.x);
                            ffma2(a1[ss], wv.y, xv.y);
                        }
                    }
                    #pragma unroll
                    for (int ss = 0; ss < 3; ss++)
                        qkvr[mat][ss] = hsum2(a0[ss], a1[ss]) + bias3[mat];
                }
                __syncwarp();   // xs consumed before next row's LN overwrites

                const float scale = 0.17677669529663687f;   // 1/sqrt(32)
                float att[3][3];
                #pragma unroll
                for (int ss = 0; ss < 3; ss++)
                    #pragma unroll
                    for (int tt = 0; tt < 3; tt++)
                        att[ss][tt] = wsum(qkvr[0][ss] * qkvr[1][tt]) * scale;

                float pool = 0.f;
                #pragma unroll
                for (int ss = 0; ss < 3; ss++) {
                    float m  = fmaxf(att[ss][0], fmaxf(att[ss][1], att[ss][2]));
                    float e0 = __expf(att[ss][0] - m);
                    float e1 = __expf(att[ss][1] - m);
                    float e2 = __expf(att[ss][2] - m);
                    float ri = 1.f / (e0 + e1 + e2);
                    pool += (e0 * qkvr[2][0] + e1 * qkvr[2][1] + e2 * qkvr[2][2]) * ri;
                }
                poolr[rr] = pool * (1.f / 3.f);
            }

            // ---- bank pooled vectors (slots 0,1) ----
            xs[0 * D + lane] = poolr[0];
            xs[1 * D + lane] = poolr[1];
            __syncwarp();

            // ---- O1 amortized over the pair ----
            float o1v[2];
            {
                const ulonglong2* w1 = reinterpret_cast<const ulonglong2*>(
                    w5 + 3 * D * WSTRIDE + lane * WSTRIDE);
                u64 a0[2] = {0, 0}, a1[2] = {0, 0};
                #pragma unroll
                for (int c = 0; c < 8; c++) {
                    ulonglong2 wv = w1[c];
                    #pragma unroll
                    for (int rr = 0; rr < 2; rr++) {
                        ulonglong2 xv = reinterpret_cast<const ulonglong2*>(xs + rr * D)[c];
                        ffma2(a0[rr], wv.x, xv.x);
                        ffma2(a1[rr], wv.y, xv.y);
                    }
                }
                #pragma unroll
                for (int rr = 0; rr < 2; rr++)
                    o1v[rr] = fmaxf(hsum2(a0[rr], a1[rr]) + bo1_l, 0.f);
            }
            __syncwarp();          // pool reads done before overwrite
            xs[0 * D + lane] = o1v[0];
            xs[1 * D + lane] = o1v[1];
            __syncwarp();

            // ---- O2 + residual + store (amortized) ----
            {
                const ulonglong2* w2 = reinterpret_cast<const ulonglong2*>(
                    w5 + 4 * D * WSTRIDE + lane * WSTRIDE);
                u64 a0[2] = {0, 0}, a1[2] = {0, 0};
                #pragma unroll
                for (int c = 0; c < 8; c++) {
                    ulonglong2 wv = w2[c];
                    #pragma unroll
                    for (int rr = 0; rr < 2; rr++) {
                        ulonglong2 xv = reinterpret_cast<const ulonglong2*>(xs + rr * D)[c];
                        ffma2(a0[rr], wv.x, xv.x);
                        ffma2(a1[rr], wv.y, xv.y);
                    }
                }
                #pragma unroll
                for (int rr = 0; rr < 2; rr++)
                    if (rr < nr)
                        out[(size_t)(row0 + r + rr * 8) * D + lane] =
                            hsum2(a0[rr], a1[rr]) + bo2_l + poolr[rr];
            }
            __syncwarp();
        }
        // no end-of-tile barrier: epi scratch dedicated; next tile's GEMM
        // barriers provide ordering.
    }
}

// ================= launch =================
extern "C" void kernel_launch(void* const* d_in, const int* in_sizes, int n_in,
                              void* d_out, int out_size)
{
    const float* f1   = (const float*)d_in[0];
    const float* f4   = (const float*)d_in[1];
    const float* fD   = (const float*)d_in[2];
    const float* Wp   = (const float*)d_in[3];
    const float* bp   = (const float*)d_in[4];
    const float* ln_g = (const float*)d_in[5];
    const float* ln_b = (const float*)d_in[6];
    const float* Wq   = (const float*)d_in[7];
    const float* bq   = (const float*)d_in[8];
    const float* Wk   = (const float*)d_in[9];
    const float* bk   = (const float*)d_in[10];
    const float* Wv   = (const float*)d_in[11];
    const float* bv   = (const float*)d_in[12];
    const float* Wo1  = (const float*)d_in[13];
    const float* bo1  = (const float*)d_in[14];
    const float* Wo2  = (const float*)d_in[15];
    const float* bo2  = (const float*)d_in[16];

    const int B = in_sizes[0] / IN_DIM;
    const int ntiles = (B + TILE_ROWS - 1) / TILE_ROWS;

    cudaFuncSetAttribute(fused_kernel, cudaFuncAttributeMaxDynamicSharedMemorySize, SMEM_SZ);

    int grid = ntiles < 304 ? ntiles : 304;   // 2 blocks x 152 SMs
    fused_kernel<<<grid, THREADS, SMEM_SZ>>>(
        f1, f4, fD, Wp, bp, ln_g, ln_b, Wq, bq, Wk, bk, Wv, bv,
        Wo1, bo1, Wo2, bo2, (float*)d_out, B, ntiles);
}